// round 5
// baseline (speedup 1.0000x reference)
#include <cuda_runtime.h>
#include <math.h>

#define NMAX 50000
#define EMAX 800000
#define H 128

// Scratch (static device globals: allowed; no allocation in kernel_launch)
__device__ float  g_deg[NMAX];
__device__ float  g_dis[NMAX];
__device__ float4 g_B0[NMAX * 32];   // h' = h @ W  (GEMM output)
__device__ float4 g_B1[NMAX * 32];   // agg ping
__device__ float4 g_B2[NMAX * 32];   // agg pong

// ---------------------------------------------------------------------------
// degree / normalization
// ---------------------------------------------------------------------------
__global__ void k_init_deg(float* __restrict__ deg, int n) {
    int i = blockIdx.x * blockDim.x + threadIdx.x;
    if (i < n) deg[i] = 1.0f;  // self-loop
}

__global__ void k_count_deg(const int* __restrict__ dst, float* __restrict__ deg, int E) {
    int i = blockIdx.x * blockDim.x + threadIdx.x;
    if (i < E) atomicAdd(&deg[dst[i]], 1.0f);
}

__global__ void k_calc_dis(const float* __restrict__ deg, float* __restrict__ dis, int n) {
    int i = blockIdx.x * blockDim.x + threadIdx.x;
    if (i < n) dis[i] = rsqrtf(deg[i]);
}

// ---------------------------------------------------------------------------
// SGEMM: C[M x 128] = A[M x 128] @ W[128 x 128], fp32
// 128x128 block tile, Kc=16, 8x8 microtile per thread, 256 threads
// ---------------------------------------------------------------------------
__global__ __launch_bounds__(256, 2) void k_gemm128(
    const float* __restrict__ A, const float* __restrict__ W,
    float* __restrict__ C, int M)
{
    __shared__ float As[16][128];  // As[k][m] (A transposed in smem)
    __shared__ float Bs[16][128];  // Bs[k][n]

    const int tid = threadIdx.x;
    const int tx  = tid & 15;       // 0..15 -> col group
    const int ty  = tid >> 4;       // 0..15 -> row group
    const int m0  = blockIdx.x << 7;

    const int ar = tid >> 2;        // 0..63  A-load row
    const int ac = (tid & 3) << 2;  // 0,4,8,12 A-load k-offset
    const int br = tid >> 5;        // 0..7   B-load k row
    const int bc = (tid & 31) << 2; // B-load col

    float acc[8][8];
#pragma unroll
    for (int i = 0; i < 8; i++)
#pragma unroll
        for (int j = 0; j < 8; j++) acc[i][j] = 0.0f;

    for (int k0 = 0; k0 < 128; k0 += 16) {
#pragma unroll
        for (int i = 0; i < 2; i++) {
            int row = m0 + ar + i * 64;
            float4 v = make_float4(0.f, 0.f, 0.f, 0.f);
            if (row < M) v = *(const float4*)(A + (size_t)row * H + k0 + ac);
            As[ac + 0][ar + i * 64] = v.x;
            As[ac + 1][ar + i * 64] = v.y;
            As[ac + 2][ar + i * 64] = v.z;
            As[ac + 3][ar + i * 64] = v.w;
        }
#pragma unroll
        for (int i = 0; i < 2; i++) {
            int kk = br + i * 8;
            *(float4*)&Bs[kk][bc] = *(const float4*)(W + (size_t)(k0 + kk) * H + bc);
        }
        __syncthreads();

#pragma unroll
        for (int k = 0; k < 16; k++) {
            float a[8], b[8];
            *(float4*)(a)     = *(const float4*)&As[k][ty * 8];
            *(float4*)(a + 4) = *(const float4*)&As[k][ty * 8 + 4];
            *(float4*)(b)     = *(const float4*)&Bs[k][tx * 8];
            *(float4*)(b + 4) = *(const float4*)&Bs[k][tx * 8 + 4];
#pragma unroll
            for (int i = 0; i < 8; i++)
#pragma unroll
                for (int j = 0; j < 8; j++)
                    acc[i][j] = fmaf(a[i], b[j], acc[i][j]);
        }
        __syncthreads();
    }

#pragma unroll
    for (int i = 0; i < 8; i++) {
        int row = m0 + ty * 8 + i;
        if (row < M) {
            *(float4*)(C + (size_t)row * H + tx * 8)     = make_float4(acc[i][0], acc[i][1], acc[i][2], acc[i][3]);
            *(float4*)(C + (size_t)row * H + tx * 8 + 4) = make_float4(acc[i][4], acc[i][5], acc[i][6], acc[i][7]);
        }
    }
}

// ---------------------------------------------------------------------------
// agg init: agg[v] = h'[v] * dis[v]^2   (self-loop contribution, also zeroes)
// ---------------------------------------------------------------------------
__global__ void k_init_agg(const float4* __restrict__ h2, const float* __restrict__ dis,
                           float4* __restrict__ agg, int total4) {
    int i = blockIdx.x * blockDim.x + threadIdx.x;
    if (i >= total4) return;
    float s = dis[i >> 5];
    s = s * s;
    float4 v = h2[i];
    v.x *= s; v.y *= s; v.z *= s; v.w *= s;
    agg[i] = v;
}

// ---------------------------------------------------------------------------
// edge scatter: one warp per edge, float4 per lane (32 lanes x 4 = 128 feats)
// agg[dst] += h'[src] * dis[src]*dis[dst]  via RED.ADD.F32x4
// ---------------------------------------------------------------------------
__global__ void k_scatter(const int* __restrict__ src, const int* __restrict__ dst,
                          const float* __restrict__ dis, const float4* __restrict__ h2,
                          float4* __restrict__ agg, int E) {
    int gt   = blockIdx.x * blockDim.x + threadIdx.x;
    int e    = gt >> 5;
    int lane = threadIdx.x & 31;
    if (e >= E) return;
    int s = __ldg(src + e);
    int d = __ldg(dst + e);
    float nrm = __ldg(dis + s) * __ldg(dis + d);
    float4 v = __ldg(h2 + (size_t)s * 32 + lane);
    v.x *= nrm; v.y *= nrm; v.z *= nrm; v.w *= nrm;
    atomicAdd(agg + (size_t)d * 32 + lane, v);   // sm_90+ vector atomic -> RED.ADD.F32x4
}

// ---------------------------------------------------------------------------
// bias + ELU (in place)
// ---------------------------------------------------------------------------
__global__ void k_bias_elu(float4* __restrict__ agg, const float4* __restrict__ b4, int total4) {
    int i = blockIdx.x * blockDim.x + threadIdx.x;
    if (i >= total4) return;
    float4 v = agg[i];
    float4 b = __ldg(b4 + (i & 31));
    v.x += b.x; v.y += b.y; v.z += b.z; v.w += b.w;
    v.x = v.x > 0.f ? v.x : expm1f(v.x);
    v.y = v.y > 0.f ? v.y : expm1f(v.y);
    v.z = v.z > 0.f ? v.z : expm1f(v.z);
    v.w = v.w > 0.f ? v.w : expm1f(v.w);
    agg[i] = v;
}

// ---------------------------------------------------------------------------
// final projection: out[v] = h[v] . Wl + bl  (warp per node)
// ---------------------------------------------------------------------------
__global__ void k_final(const float4* __restrict__ h, const float4* __restrict__ Wl4,
                        const float* __restrict__ bl, float* __restrict__ out, int n) {
    int gt   = blockIdx.x * blockDim.x + threadIdx.x;
    int v    = gt >> 5;
    int lane = threadIdx.x & 31;
    if (v >= n) return;
    float4 hv = __ldg(h + (size_t)v * 32 + lane);
    float4 wv = __ldg(Wl4 + lane);
    float p = hv.x * wv.x + hv.y * wv.y + hv.z * wv.z + hv.w * wv.w;
#pragma unroll
    for (int o = 16; o > 0; o >>= 1) p += __shfl_xor_sync(0xffffffff, p, o);
    if (lane == 0) out[v] = p + __ldg(bl);
}

// ---------------------------------------------------------------------------
extern "C" void kernel_launch(void* const* d_in, const int* in_sizes, int n_in,
                              void* d_out, int out_size) {
    const float* x  = (const float*)d_in[0];
    const float* Ws = (const float*)d_in[1];
    const float* bs = (const float*)d_in[2];
    const float* Wl = (const float*)d_in[3];
    const float* bl = (const float*)d_in[4];
    const int*   ei = (const int*)d_in[5];

    int n = in_sizes[0] / H;      // 50000
    int E = in_sizes[5] / 2;      // 800000
    const int* src = ei;
    const int* dst = ei + E;

    float *deg, *dis;
    float4 *B0, *B1, *B2;
    cudaGetSymbolAddress((void**)&deg, g_deg);
    cudaGetSymbolAddress((void**)&dis, g_dis);
    cudaGetSymbolAddress((void**)&B0,  g_B0);
    cudaGetSymbolAddress((void**)&B1,  g_B1);
    cudaGetSymbolAddress((void**)&B2,  g_B2);

    const int T = 256;
    int total4 = n * 32;

    // degree + norm
    k_init_deg<<<(n + T - 1) / T, T>>>(deg, n);
    k_count_deg<<<(E + T - 1) / T, T>>>(dst, deg, E);
    k_calc_dis<<<(n + T - 1) / T, T>>>(deg, dis, n);

    int gemm_blocks = (n + 127) >> 7;
    int ew_blocks   = (total4 + T - 1) / T;
    int sc_blocks   = ((E * 32) + T - 1) / T;

    // 3 GCN layers
    for (int l = 0; l < 3; l++) {
        const float* hcur = (l == 0) ? x : (const float*)((l == 1) ? B1 : B2);
        float4* agg = (l == 1) ? B2 : B1;

        k_gemm128<<<gemm_blocks, T>>>(hcur, Ws + (size_t)l * H * H, (float*)B0, n);
        k_init_agg<<<ew_blocks, T>>>(B0, dis, agg, total4);
        k_scatter<<<sc_blocks, T>>>(src, dst, dis, B0, agg, E);
        k_bias_elu<<<ew_blocks, T>>>(agg, (const float4*)(bs + (size_t)l * H), total4);
    }

    // final linear (h in B1 after layer 2)
    k_final<<<(n * 32 + T - 1) / T, T>>>(B1, (const float4*)Wl, bl, (float*)d_out, n);
}

// round 6
// speedup vs baseline: 1.7068x; 1.7068x over previous
#include <cuda_runtime.h>
#include <math.h>

#define NMAX 50000
#define EMAX 800000
#define H 128

// Scratch (device globals — no allocation anywhere)
__device__ int    g_cnt[NMAX];        // histogram / fill counters
__device__ float  g_dis[NMAX];        // deg^-1/2
__device__ int    g_rowptr[NMAX + 1]; // CSR row pointers (by dst)
__device__ int    g_bsum[64];         // scan block sums
__device__ int    g_csrc[EMAX];       // CSR src indices
__device__ float  g_cnrm[EMAX];       // CSR edge norms dis[s]*dis[d]
__device__ float4 g_B0[NMAX * 32];    // h' = h @ W (GEMM out)
__device__ float4 g_B1[NMAX * 32];    // layer ping
__device__ float4 g_B2[NMAX * 32];    // layer pong

// ---------------------------------------------------------------------------
// CSR build: zero, histogram(dst), dis, scan, fill
// ---------------------------------------------------------------------------
__global__ void k_zero(int* __restrict__ p, int n) {
    int i = blockIdx.x * blockDim.x + threadIdx.x;
    if (i < n) p[i] = 0;
}

__global__ void k_hist(const int* __restrict__ dst, int* __restrict__ cnt, int E) {
    int i = blockIdx.x * blockDim.x + threadIdx.x;
    if (i < E) atomicAdd(&cnt[dst[i]], 1);
}

__global__ void k_calc_dis(const int* __restrict__ cnt, float* __restrict__ dis, int n) {
    int i = blockIdx.x * blockDim.x + threadIdx.x;
    if (i < n) dis[i] = rsqrtf((float)(cnt[i] + 1));  // +1 self loop
}

// exclusive scan, 1024 elems/block (256 thr x 4)
__global__ void k_scan_a(const int* __restrict__ cnt, int* __restrict__ out,
                         int* __restrict__ bsum, int n) {
    __shared__ int sh[256];
    int tid = threadIdx.x;
    int idx0 = blockIdx.x * 1024 + tid * 4;
    int it[4];
#pragma unroll
    for (int i = 0; i < 4; i++) it[i] = (idx0 + i < n) ? cnt[idx0 + i] : 0;
    int sum = it[0] + it[1] + it[2] + it[3];
    sh[tid] = sum;
    __syncthreads();
#pragma unroll
    for (int off = 1; off < 256; off <<= 1) {
        int v = (tid >= off) ? sh[tid - off] : 0;
        __syncthreads();
        sh[tid] += v;
        __syncthreads();
    }
    int run = sh[tid] - sum;  // exclusive prefix for this thread
#pragma unroll
    for (int i = 0; i < 4; i++) {
        if (idx0 + i < n) out[idx0 + i] = run;
        run += it[i];
    }
    if (tid == 255) bsum[blockIdx.x] = sh[255];
}

__global__ void k_scan_b(int* __restrict__ bsum, int nb) {
    if (threadIdx.x == 0) {
        int acc = 0;
        for (int i = 0; i < nb; i++) { int v = bsum[i]; bsum[i] = acc; acc += v; }
    }
}

__global__ void k_scan_c(int* __restrict__ out, const int* __restrict__ bsum, int n, int E) {
    int i = blockIdx.x * blockDim.x + threadIdx.x;
    if (i < n) out[i] += bsum[i >> 10];
    if (i == 0) out[n] = E;
}

__global__ void k_fill(const int* __restrict__ src, const int* __restrict__ dst,
                       const float* __restrict__ dis, const int* __restrict__ rowptr,
                       int* __restrict__ fill, int* __restrict__ csrc,
                       float* __restrict__ cnrm, int E) {
    int e = blockIdx.x * blockDim.x + threadIdx.x;
    if (e >= E) return;
    int s = src[e], d = dst[e];
    int pos = rowptr[d] + atomicAdd(&fill[d], 1);
    csrc[pos] = s;
    cnrm[pos] = dis[s] * dis[d];
}

// ---------------------------------------------------------------------------
// SGEMM: C[M x 128] = A[M x 128] @ W[128 x 128], fp32 (unchanged, ~86%-of-floor)
// ---------------------------------------------------------------------------
__global__ __launch_bounds__(256, 2) void k_gemm128(
    const float* __restrict__ A, const float* __restrict__ W,
    float* __restrict__ C, int M)
{
    __shared__ float As[16][128];
    __shared__ float Bs[16][128];

    const int tid = threadIdx.x;
    const int tx  = tid & 15;
    const int ty  = tid >> 4;
    const int m0  = blockIdx.x << 7;

    const int ar = tid >> 2;
    const int ac = (tid & 3) << 2;
    const int br = tid >> 5;
    const int bc = (tid & 31) << 2;

    float acc[8][8];
#pragma unroll
    for (int i = 0; i < 8; i++)
#pragma unroll
        for (int j = 0; j < 8; j++) acc[i][j] = 0.0f;

    for (int k0 = 0; k0 < 128; k0 += 16) {
#pragma unroll
        for (int i = 0; i < 2; i++) {
            int row = m0 + ar + i * 64;
            float4 v = make_float4(0.f, 0.f, 0.f, 0.f);
            if (row < M) v = *(const float4*)(A + (size_t)row * H + k0 + ac);
            As[ac + 0][ar + i * 64] = v.x;
            As[ac + 1][ar + i * 64] = v.y;
            As[ac + 2][ar + i * 64] = v.z;
            As[ac + 3][ar + i * 64] = v.w;
        }
#pragma unroll
        for (int i = 0; i < 2; i++) {
            int kk = br + i * 8;
            *(float4*)&Bs[kk][bc] = *(const float4*)(W + (size_t)(k0 + kk) * H + bc);
        }
        __syncthreads();

#pragma unroll
        for (int k = 0; k < 16; k++) {
            float a[8], b[8];
            *(float4*)(a)     = *(const float4*)&As[k][ty * 8];
            *(float4*)(a + 4) = *(const float4*)&As[k][ty * 8 + 4];
            *(float4*)(b)     = *(const float4*)&Bs[k][tx * 8];
            *(float4*)(b + 4) = *(const float4*)&Bs[k][tx * 8 + 4];
#pragma unroll
            for (int i = 0; i < 8; i++)
#pragma unroll
                for (int j = 0; j < 8; j++)
                    acc[i][j] = fmaf(a[i], b[j], acc[i][j]);
        }
        __syncthreads();
    }

#pragma unroll
    for (int i = 0; i < 8; i++) {
        int row = m0 + ty * 8 + i;
        if (row < M) {
            *(float4*)(C + (size_t)row * H + tx * 8)     = make_float4(acc[i][0], acc[i][1], acc[i][2], acc[i][3]);
            *(float4*)(C + (size_t)row * H + tx * 8 + 4) = make_float4(acc[i][4], acc[i][5], acc[i][6], acc[i][7]);
        }
    }
}

// ---------------------------------------------------------------------------
// Fused gather + self-loop + bias + ELU.  One warp per dst node; lane = 4 feats.
// out[v] = elu( dis[v]^2 * h'[v] + sum_j h'[src_j]*nrm_j + b )
// ---------------------------------------------------------------------------
__global__ __launch_bounds__(256) void k_gather(
    const int* __restrict__ rowptr, const int* __restrict__ csrc,
    const float* __restrict__ cnrm, const float* __restrict__ dis,
    const float4* __restrict__ h2, const float4* __restrict__ b4,
    float4* __restrict__ out, int n)
{
    int gt   = blockIdx.x * blockDim.x + threadIdx.x;
    int v    = gt >> 5;
    int lane = threadIdx.x & 31;
    if (v >= n) return;

    float s = dis[v];
    float selfw = s * s;
    float4 acc = __ldg(h2 + (size_t)v * 32 + lane);
    acc.x *= selfw; acc.y *= selfw; acc.z *= selfw; acc.w *= selfw;

    int j   = __ldg(rowptr + v);
    int end = __ldg(rowptr + v + 1);

    // unroll x2 for MLP
    for (; j + 1 < end; j += 2) {
        int   s0 = __ldg(csrc + j),     s1 = __ldg(csrc + j + 1);
        float w0 = __ldg(cnrm + j),     w1 = __ldg(cnrm + j + 1);
        float4 t0 = __ldg(h2 + (size_t)s0 * 32 + lane);
        float4 t1 = __ldg(h2 + (size_t)s1 * 32 + lane);
        acc.x = fmaf(t0.x, w0, acc.x); acc.x = fmaf(t1.x, w1, acc.x);
        acc.y = fmaf(t0.y, w0, acc.y); acc.y = fmaf(t1.y, w1, acc.y);
        acc.z = fmaf(t0.z, w0, acc.z); acc.z = fmaf(t1.z, w1, acc.z);
        acc.w = fmaf(t0.w, w0, acc.w); acc.w = fmaf(t1.w, w1, acc.w);
    }
    if (j < end) {
        int   s0 = __ldg(csrc + j);
        float w0 = __ldg(cnrm + j);
        float4 t0 = __ldg(h2 + (size_t)s0 * 32 + lane);
        acc.x = fmaf(t0.x, w0, acc.x);
        acc.y = fmaf(t0.y, w0, acc.y);
        acc.z = fmaf(t0.z, w0, acc.z);
        acc.w = fmaf(t0.w, w0, acc.w);
    }

    float4 b = __ldg(b4 + lane);
    acc.x += b.x; acc.y += b.y; acc.z += b.z; acc.w += b.w;
    acc.x = acc.x > 0.f ? acc.x : expm1f(acc.x);
    acc.y = acc.y > 0.f ? acc.y : expm1f(acc.y);
    acc.z = acc.z > 0.f ? acc.z : expm1f(acc.z);
    acc.w = acc.w > 0.f ? acc.w : expm1f(acc.w);
    out[(size_t)v * 32 + lane] = acc;
}

// ---------------------------------------------------------------------------
// final projection: out[v] = h[v] . Wl + bl  (warp per node)
// ---------------------------------------------------------------------------
__global__ void k_final(const float4* __restrict__ h, const float4* __restrict__ Wl4,
                        const float* __restrict__ bl, float* __restrict__ out, int n) {
    int gt   = blockIdx.x * blockDim.x + threadIdx.x;
    int v    = gt >> 5;
    int lane = threadIdx.x & 31;
    if (v >= n) return;
    float4 hv = __ldg(h + (size_t)v * 32 + lane);
    float4 wv = __ldg(Wl4 + lane);
    float p = hv.x * wv.x + hv.y * wv.y + hv.z * wv.z + hv.w * wv.w;
#pragma unroll
    for (int o = 16; o > 0; o >>= 1) p += __shfl_xor_sync(0xffffffff, p, o);
    if (lane == 0) out[v] = p + __ldg(bl);
}

// ---------------------------------------------------------------------------
extern "C" void kernel_launch(void* const* d_in, const int* in_sizes, int n_in,
                              void* d_out, int out_size) {
    const float* x  = (const float*)d_in[0];
    const float* Ws = (const float*)d_in[1];
    const float* bs = (const float*)d_in[2];
    const float* Wl = (const float*)d_in[3];
    const float* bl = (const float*)d_in[4];
    const int*   ei = (const int*)d_in[5];

    int n = in_sizes[0] / H;      // 50000
    int E = in_sizes[5] / 2;      // 800000
    const int* src = ei;
    const int* dst = ei + E;

    int *cnt, *rowptr, *bsum, *csrc;
    float *dis, *cnrm;
    float4 *B0, *B1, *B2;
    cudaGetSymbolAddress((void**)&cnt,    g_cnt);
    cudaGetSymbolAddress((void**)&dis,    g_dis);
    cudaGetSymbolAddress((void**)&rowptr, g_rowptr);
    cudaGetSymbolAddress((void**)&bsum,   g_bsum);
    cudaGetSymbolAddress((void**)&csrc,   g_csrc);
    cudaGetSymbolAddress((void**)&cnrm,   g_cnrm);
    cudaGetSymbolAddress((void**)&B0,     g_B0);
    cudaGetSymbolAddress((void**)&B1,     g_B1);
    cudaGetSymbolAddress((void**)&B2,     g_B2);

    const int T = 256;
    int nb_n = (n + T - 1) / T;
    int nb_E = (E + T - 1) / T;
    int nb_scan = (n + 1023) / 1024;

    // ---- CSR build (once per launch) ----
    k_zero<<<nb_n, T>>>(cnt, n);
    k_hist<<<nb_E, T>>>(dst, cnt, E);
    k_calc_dis<<<nb_n, T>>>(cnt, dis, n);
    k_scan_a<<<nb_scan, T>>>(cnt, rowptr, bsum, n);
    k_scan_b<<<1, 32>>>(bsum, nb_scan);
    k_scan_c<<<nb_n, T>>>(rowptr, bsum, n, E);
    k_zero<<<nb_n, T>>>(cnt, n);  // reuse as fill counters
    k_fill<<<nb_E, T>>>(src, dst, dis, rowptr, cnt, csrc, cnrm, E);

    int gemm_blocks   = (n + 127) >> 7;
    int gather_blocks = (n * 32 + T - 1) / T;

    // ---- 3 GCN layers (gather fuses agg + bias + ELU) ----
    for (int l = 0; l < 3; l++) {
        const float* hcur = (l == 0) ? x : (const float*)((l == 1) ? B1 : B2);
        float4* hout = (l == 1) ? B2 : B1;

        k_gemm128<<<gemm_blocks, T>>>(hcur, Ws + (size_t)l * H * H, (float*)B0, n);
        k_gather<<<gather_blocks, T>>>(rowptr, csrc, cnrm, dis, B0,
                                       (const float4*)(bs + (size_t)l * H), hout, n);
    }

    // final linear (h in B1 after layer 2)
    k_final<<<gather_blocks, T>>>(B1, (const float4*)Wl, bl, (float*)d_out, n);
}